// round 10
// baseline (speedup 1.0000x reference)
#include <cuda_runtime.h>
#include <cuda_fp16.h>
#include <mma.h>

using namespace nvcuda;

#define F 128
#define N_NODES_MAX 100000
#define N_ROWS_PAD 100096  // 1564 * 64 (GEMM tile M=64)

// fp16 support (only consumer is the scatter)
__device__ __half g_support_h[(size_t)N_ROWS_PAD * F];

// ---------------------------------------------------------------------------
// GEMM: support_h[n,128] = fp16( x[n,128] @ w[128,128] ), FP16 x1, fp32 acc.
// Also writes out[row] = bias (fused init; scatter RED-adds on top).
// Structure from proven R9 kernel: block 128 thr (4 warps), tile 64x128,
// warp tile 32x64, K tiled 4x32, 3 CTAs/SM. W converted fp32->fp16 in-block.
// ---------------------------------------------------------------------------
__global__ void __launch_bounds__(128, 3) gemm_fp16_kernel(
    const float* __restrict__ x, const float* __restrict__ w,
    const float* __restrict__ bias, float* __restrict__ out, int n) {
    __shared__ __half xs[64][40];    // 5.0 KB
    __shared__ __half ws[32][136];   // 8.5 KB
    __shared__ float bs[F];          // 0.5 KB bias copy

    const int tid = threadIdx.x;
    const int wid = tid >> 5;
    const int lane = tid & 31;
    const int warp_m = wid & 1;   // 32-row band
    const int warp_n = wid >> 1;  // 64-col band
    const int row0 = blockIdx.x * 64;

    bs[tid] = __ldg(&bias[tid]);  // blockDim == 128 == F

    wmma::fragment<wmma::accumulator, 16, 16, 16, float> acc[2][4];
    #pragma unroll
    for (int i = 0; i < 2; i++)
        #pragma unroll
        for (int j = 0; j < 4; j++) wmma::fill_fragment(acc[i][j], 0.0f);

    for (int kt = 0; kt < 4; kt++) {
        // x tile 64x32: 512 float4, 4 per thread; convert to fp16
        #pragma unroll
        for (int i = tid; i < 512; i += 128) {
            int r = i >> 3;
            int c = (i & 7) * 4;
            int row = row0 + r;
            float4 v = make_float4(0.f, 0.f, 0.f, 0.f);
            if (row < n)
                v = *(const float4*)&x[(size_t)row * F + kt * 32 + c];
            __half hb[4] = {__float2half_rn(v.x), __float2half_rn(v.y),
                            __float2half_rn(v.z), __float2half_rn(v.w)};
            *(uint2*)&xs[r][c] = *(uint2*)hb;
        }
        // w tile 32x128: load fp32 (L2-hot), convert to fp16 in-block
        #pragma unroll
        for (int i = tid; i < 1024; i += 128) {
            int r = i >> 5;            // 32 float4-chunks per row
            int c = (i & 31) * 4;
            float4 v = *(const float4*)&w[(size_t)(kt * 32 + r) * F + c];
            __half hb[4] = {__float2half_rn(v.x), __float2half_rn(v.y),
                            __float2half_rn(v.z), __float2half_rn(v.w)};
            *(uint2*)&ws[r][c] = *(uint2*)hb;
        }
        __syncthreads();

        #pragma unroll
        for (int ks = 0; ks < 2; ks++) {  // 2 k-steps of 16
            wmma::fragment<wmma::matrix_a, 16, 16, 16, __half,
                           wmma::row_major> a[2];
            #pragma unroll
            for (int i = 0; i < 2; i++)
                wmma::load_matrix_sync(a[i],
                                       &xs[warp_m * 32 + i * 16][ks * 16], 40);
            #pragma unroll
            for (int j = 0; j < 4; j++) {
                wmma::fragment<wmma::matrix_b, 16, 16, 16, __half,
                               wmma::row_major> b;
                wmma::load_matrix_sync(b,
                                       &ws[ks * 16][warp_n * 64 + j * 16], 136);
                #pragma unroll
                for (int i = 0; i < 2; i++)
                    wmma::mma_sync(acc[i][j], a[i], b, acc[i][j]);
            }
        }
        __syncthreads();
    }

    // Epilogue: stage each 16x16 frag via smem, write fp16 support, and
    // write out[row] = bias (fused bias init).
    float* stage = (float*)&xs[0][0] + wid * 320;  // 16x20 floats per warp
    #pragma unroll
    for (int i = 0; i < 2; i++)
        #pragma unroll
        for (int j = 0; j < 4; j++) {
            wmma::store_matrix_sync(stage, acc[i][j], 20, wmma::mem_row_major);
            __syncwarp();
            int r = lane >> 1;
            int c = (lane & 1) * 8;
            int col0 = warp_n * 64 + j * 16 + c;
            __half hbuf[8];
            #pragma unroll
            for (int q = 0; q < 8; q++)
                hbuf[q] = __float2half_rn(stage[r * 20 + c + q]);
            size_t row = (size_t)row0 + warp_m * 32 + i * 16 + r;
            *(uint4*)&g_support_h[row * F + col0] = *(uint4*)hbuf;
            if ((int)row < n) {
                *(float4*)&out[row * F + col0] = *(float4*)&bs[col0];
                *(float4*)&out[row * F + col0 + 4] = *(float4*)&bs[col0 + 4];
            }
            __syncwarp();
        }
}

// ---------------------------------------------------------------------------
// Edge scatter (verbatim R9): out[rows[e]] += support_h[cols[e]] * vals[e]
// Warp owns 32 edges: coalesced index loads + shfl broadcast.
// 8B fp16 gather per lane; one red.global.add.v4.f32 per lane per edge.
// ---------------------------------------------------------------------------
__global__ void __launch_bounds__(256) scatter_kernel(
    const float* __restrict__ vals0, const int* __restrict__ rows0,
    const int* __restrict__ cols0,
    const float* __restrict__ vals1, const int* __restrict__ rows1,
    const int* __restrict__ cols1,
    float* __restrict__ out, int E) {
    int gw = (blockIdx.x * blockDim.x + threadIdx.x) >> 5;
    int lane = threadIdx.x & 31;
    int warps_per_set = (E + 31) >> 5;
    if (gw >= 2 * warps_per_set) return;

    const float* vals;
    const int* rows;
    const int* cols;
    int wset = gw;
    if (gw < warps_per_set) {
        vals = vals0; rows = rows0; cols = cols0;
    } else {
        vals = vals1; rows = rows1; cols = cols1; wset = gw - warps_per_set;
    }
    int base = wset * 32;

    int e = base + lane;
    bool valid = e < E;
    float v = valid ? __ldg(&vals[e]) : 0.f;
    int r = valid ? __ldg(&rows[e]) : 0;
    int c = valid ? __ldg(&cols[e]) : 0;

    int cnt = min(32, E - base);
    const uint2* sup = (const uint2*)g_support_h;

    #pragma unroll 4
    for (int i = 0; i < cnt; i++) {
        int rr = __shfl_sync(0xffffffff, r, i);
        int cc = __shfl_sync(0xffffffff, c, i);
        float vv = __shfl_sync(0xffffffff, v, i);

        uint2 packed = __ldg(&sup[(size_t)cc * (F / 4) + lane]);
        float2 f01 = __half22float2(*(__half2*)&packed.x);
        float2 f23 = __half22float2(*(__half2*)&packed.y);

        float* dst = out + (size_t)rr * F + lane * 4;
        asm volatile("red.global.add.v4.f32 [%0], {%1,%2,%3,%4};"
                     :: "l"(dst), "f"(f01.x * vv), "f"(f01.y * vv),
                        "f"(f23.x * vv), "f"(f23.y * vv)
                     : "memory");
    }
}

// ---------------------------------------------------------------------------
// kernel_launch
// inputs: x, weight, bias, vals0, vals1, rows0, cols0, rows1, cols1
// ---------------------------------------------------------------------------
extern "C" void kernel_launch(void* const* d_in, const int* in_sizes, int n_in,
                              void* d_out, int out_size) {
    const float* x     = (const float*)d_in[0];
    const float* w     = (const float*)d_in[1];
    const float* bias  = (const float*)d_in[2];
    const float* vals0 = (const float*)d_in[3];
    const float* vals1 = (const float*)d_in[4];
    const int* rows0   = (const int*)d_in[5];
    const int* cols0   = (const int*)d_in[6];
    const int* rows1   = (const int*)d_in[7];
    const int* cols1   = (const int*)d_in[8];
    float* out = (float*)d_out;

    int n = in_sizes[0] / F;   // 100000
    int E = in_sizes[3];       // 600000

    // 1) support_h = fp16(x @ W); out = bias (both fused in one kernel)
    gemm_fp16_kernel<<<(n + 63) / 64, 128>>>(x, w, bias, out, n);

    // 2) scatter both edge sets (one launch, vector reds)
    long long total_warps = 2LL * ((E + 31) / 32);
    int sblocks = (int)((total_warps * 32 + 255) / 256);
    scatter_kernel<<<sblocks, 256>>>(vals0, rows0, cols0, vals1, rows1, cols1,
                                     out, E);
}

// round 12
// speedup vs baseline: 1.3267x; 1.3267x over previous
#include <cuda_runtime.h>
#include <cuda_fp16.h>
#include <mma.h>

using namespace nvcuda;

#define F 128
#define N_NODES_MAX 100000
#define N_ROWS_PAD 100096  // 1564 * 64 (GEMM tile M=64)

typedef unsigned int u32;

// fp16 support (only consumer is the scatter)
__device__ __half g_support_h[(size_t)N_ROWS_PAD * F];
// fp16 accumulator: init = half(bias), scatter RED-adds, finalize converts
__device__ __half g_acc_h[(size_t)N_ROWS_PAD * F];

// ---------------------------------------------------------------------------
// GEMM (mainloop verbatim R10): support_h = fp16(x @ W), FP16 x1, fp32 acc.
// Epilogue: writes fp16 support AND g_acc_h[row] = half(bias).
// ---------------------------------------------------------------------------
__global__ void __launch_bounds__(128, 3) gemm_fp16_kernel(
    const float* __restrict__ x, const float* __restrict__ w,
    const float* __restrict__ bias, int n) {
    __shared__ __half xs[64][40];    // 5.0 KB
    __shared__ __half ws[32][136];   // 8.5 KB
    __shared__ __half bs_h[F];       // bias in fp16

    const int tid = threadIdx.x;
    const int wid = tid >> 5;
    const int lane = tid & 31;
    const int warp_m = wid & 1;
    const int warp_n = wid >> 1;
    const int row0 = blockIdx.x * 64;

    bs_h[tid] = __float2half_rn(__ldg(&bias[tid]));  // blockDim == 128 == F

    wmma::fragment<wmma::accumulator, 16, 16, 16, float> acc[2][4];
    #pragma unroll
    for (int i = 0; i < 2; i++)
        #pragma unroll
        for (int j = 0; j < 4; j++) wmma::fill_fragment(acc[i][j], 0.0f);

    for (int kt = 0; kt < 4; kt++) {
        #pragma unroll
        for (int i = tid; i < 512; i += 128) {
            int r = i >> 3;
            int c = (i & 7) * 4;
            int row = row0 + r;
            float4 v = make_float4(0.f, 0.f, 0.f, 0.f);
            if (row < n)
                v = *(const float4*)&x[(size_t)row * F + kt * 32 + c];
            __half hb[4] = {__float2half_rn(v.x), __float2half_rn(v.y),
                            __float2half_rn(v.z), __float2half_rn(v.w)};
            *(uint2*)&xs[r][c] = *(uint2*)hb;
        }
        #pragma unroll
        for (int i = tid; i < 1024; i += 128) {
            int r = i >> 5;
            int c = (i & 31) * 4;
            float4 v = *(const float4*)&w[(size_t)(kt * 32 + r) * F + c];
            __half hb[4] = {__float2half_rn(v.x), __float2half_rn(v.y),
                            __float2half_rn(v.z), __float2half_rn(v.w)};
            *(uint2*)&ws[r][c] = *(uint2*)hb;
        }
        __syncthreads();

        #pragma unroll
        for (int ks = 0; ks < 2; ks++) {
            wmma::fragment<wmma::matrix_a, 16, 16, 16, __half,
                           wmma::row_major> a[2];
            #pragma unroll
            for (int i = 0; i < 2; i++)
                wmma::load_matrix_sync(a[i],
                                       &xs[warp_m * 32 + i * 16][ks * 16], 40);
            #pragma unroll
            for (int j = 0; j < 4; j++) {
                wmma::fragment<wmma::matrix_b, 16, 16, 16, __half,
                               wmma::row_major> b;
                wmma::load_matrix_sync(b,
                                       &ws[ks * 16][warp_n * 64 + j * 16], 136);
                #pragma unroll
                for (int i = 0; i < 2; i++)
                    wmma::mma_sync(acc[i][j], a[i], b, acc[i][j]);
            }
        }
        __syncthreads();
    }

    // Epilogue: fp16 support + fp16 bias init of accumulator
    float* stage = (float*)&xs[0][0] + wid * 320;
    #pragma unroll
    for (int i = 0; i < 2; i++)
        #pragma unroll
        for (int j = 0; j < 4; j++) {
            wmma::store_matrix_sync(stage, acc[i][j], 20, wmma::mem_row_major);
            __syncwarp();
            int r = lane >> 1;
            int c = (lane & 1) * 8;
            int col0 = warp_n * 64 + j * 16 + c;
            __half hbuf[8];
            #pragma unroll
            for (int q = 0; q < 8; q++)
                hbuf[q] = __float2half_rn(stage[r * 20 + c + q]);
            size_t row = (size_t)row0 + warp_m * 32 + i * 16 + r;
            *(uint4*)&g_support_h[row * F + col0] = *(uint4*)hbuf;
            *(uint4*)&g_acc_h[row * F + col0] = *(uint4*)&bs_h[col0];
            __syncwarp();
        }
}

// ---------------------------------------------------------------------------
// Edge scatter: g_acc_h[rows[e]] += support_h[cols[e]] * vals[e]  (fp16 REDs)
// Warp owns 32 edges, processes 2 per iteration: lanes 0-15 -> edge 2i,
// lanes 16-31 -> edge 2i+1. Each lane: 16B gather (8 halves), fp32 multiply,
// one red.global.add.noftz.v4.f16x2 (16B, 8 halves).
// ---------------------------------------------------------------------------
__global__ void __launch_bounds__(256) scatter_kernel(
    const float* __restrict__ vals0, const int* __restrict__ rows0,
    const int* __restrict__ cols0,
    const float* __restrict__ vals1, const int* __restrict__ rows1,
    const int* __restrict__ cols1, int E) {
    int gw = (blockIdx.x * blockDim.x + threadIdx.x) >> 5;
    int lane = threadIdx.x & 31;
    int warps_per_set = (E + 31) >> 5;
    if (gw >= 2 * warps_per_set) return;

    const float* vals;
    const int* rows;
    const int* cols;
    int wset = gw;
    if (gw < warps_per_set) {
        vals = vals0; rows = rows0; cols = cols0;
    } else {
        vals = vals1; rows = rows1; cols = cols1; wset = gw - warps_per_set;
    }
    int base = wset * 32;

    int e = base + lane;
    bool valid = e < E;
    float v = valid ? __ldg(&vals[e]) : 0.f;
    int r = valid ? __ldg(&rows[e]) : 0;
    int c = valid ? __ldg(&cols[e]) : 0;

    int cnt = min(32, E - base);
    int hf = lane >> 4;     // 0: edge 2i, 1: edge 2i+1
    int sub = lane & 15;    // feature chunk (8 halves each)
    const uint4* sup = (const uint4*)g_support_h;  // 8 halves per uint4
    int pairs = (cnt + 1) >> 1;

    #pragma unroll 4
    for (int i = 0; i < pairs; i++) {
        int idx = 2 * i + hf;
        int rr = __shfl_sync(0xffffffff, r, idx);
        int cc = __shfl_sync(0xffffffff, c, idx);
        float vv = __shfl_sync(0xffffffff, v, idx);
        if (idx < cnt) {
            uint4 p = __ldg(&sup[(size_t)cc * (F / 8) + sub]);
            u32 pk[4] = {p.x, p.y, p.z, p.w};
            u32 mk[4];
            #pragma unroll
            for (int q = 0; q < 4; q++) {
                float2 f = __half22float2(*(__half2*)&pk[q]);
                __half2 h = __floats2half2_rn(f.x * vv, f.y * vv);
                mk[q] = *(u32*)&h;
            }
            __half* dst = g_acc_h + (size_t)rr * F + sub * 8;
            asm volatile(
                "red.global.add.noftz.v4.f16x2 [%0], {%1,%2,%3,%4};"
                :: "l"(dst), "r"(mk[0]), "r"(mk[1]), "r"(mk[2]), "r"(mk[3])
                : "memory");
        }
    }
}

// ---------------------------------------------------------------------------
// Finalize: out[i] = float(g_acc_h[i])
// ---------------------------------------------------------------------------
__global__ void finalize_kernel(float* __restrict__ out, int n) {
    size_t idx = (size_t)blockIdx.x * blockDim.x + threadIdx.x;
    size_t total = (size_t)n * (F / 4);
    const uint2* acc = (const uint2*)g_acc_h;  // 4 halves
    float4* out4 = (float4*)out;
    for (size_t i = idx; i < total; i += (size_t)gridDim.x * blockDim.x) {
        uint2 p = acc[i];
        float2 f01 = __half22float2(*(__half2*)&p.x);
        float2 f23 = __half22float2(*(__half2*)&p.y);
        out4[i] = make_float4(f01.x, f01.y, f23.x, f23.y);
    }
}

// ---------------------------------------------------------------------------
// kernel_launch
// inputs: x, weight, bias, vals0, vals1, rows0, cols0, rows1, cols1
// ---------------------------------------------------------------------------
extern "C" void kernel_launch(void* const* d_in, const int* in_sizes, int n_in,
                              void* d_out, int out_size) {
    const float* x     = (const float*)d_in[0];
    const float* w     = (const float*)d_in[1];
    const float* bias  = (const float*)d_in[2];
    const float* vals0 = (const float*)d_in[3];
    const float* vals1 = (const float*)d_in[4];
    const int* rows0   = (const int*)d_in[5];
    const int* cols0   = (const int*)d_in[6];
    const int* rows1   = (const int*)d_in[7];
    const int* cols1   = (const int*)d_in[8];
    float* out = (float*)d_out;

    int n = in_sizes[0] / F;   // 100000
    int E = in_sizes[3];       // 600000

    // 1) support_h = fp16(x @ W); g_acc_h = half(bias)
    gemm_fp16_kernel<<<(n + 63) / 64, 128>>>(x, w, bias, n);

    // 2) scatter both edge sets (fp16 packed REDs)
    long long total_warps = 2LL * ((E + 31) / 32);
    int sblocks = (int)((total_warps * 32 + 255) / 256);
    scatter_kernel<<<sblocks, 256>>>(vals0, rows0, cols0, vals1, rows1, cols1,
                                     E);

    // 3) out = float(g_acc_h)
    finalize_kernel<<<2048, 256>>>(out, n);
}

// round 14
// speedup vs baseline: 1.3357x; 1.0067x over previous
#include <cuda_runtime.h>
#include <cuda_fp16.h>
#include <mma.h>

using namespace nvcuda;

#define F 128
#define N_NODES_MAX 100000
#define N_ROWS_PAD 100096  // 1564 * 64 (GEMM tile M=64)

typedef unsigned int u32;

// fp16 support (only consumer is the scatter)
__device__ __half g_support_h[(size_t)N_ROWS_PAD * F];
// fp16 accumulator: init = half(bias), scatter RED-adds, finalize converts
__device__ __half g_acc_h[(size_t)N_ROWS_PAD * F];

// ---------------------------------------------------------------------------
// GEMM: support_h = fp16(x @ W), FP16 x1, fp32 acc; g_acc_h[row] = half(bias).
// Block 256 thr (8 warps), tile 64(M) x 128(N), warp tile 32x32
// (warp_m = wid&1, warp_n = wid>>1). K tiled 4x32. 2 CTAs/SM.
// Shared memory carved from one buffer: xs | ws, reused as epilogue stage.
// ---------------------------------------------------------------------------
__global__ void __launch_bounds__(256, 2) gemm_fp16_kernel(
    const float* __restrict__ x, const float* __restrict__ w,
    const float* __restrict__ bias, int n) {
    __shared__ __align__(16) char smem_raw[14336];  // 14 KB
    __shared__ __half bs_h[F];

    __half (*xs)[40] = (__half(*)[40])smem_raw;               // 64x40 = 5120 B
    __half (*ws)[136] = (__half(*)[136])(smem_raw + 5120);    // 32x136 = 8704 B

    const int tid = threadIdx.x;
    const int wid = tid >> 5;
    const int lane = tid & 31;
    const int warp_m = wid & 1;   // 32-row band
    const int warp_n = wid >> 1;  // 32-col band (4 bands)
    const int row0 = blockIdx.x * 64;

    if (tid < F) bs_h[tid] = __float2half_rn(__ldg(&bias[tid]));

    wmma::fragment<wmma::accumulator, 16, 16, 16, float> acc[2][2];
    #pragma unroll
    for (int i = 0; i < 2; i++)
        #pragma unroll
        for (int j = 0; j < 2; j++) wmma::fill_fragment(acc[i][j], 0.0f);

    for (int kt = 0; kt < 4; kt++) {
        // x tile 64x32: 512 float4, 2 per thread; convert to fp16
        #pragma unroll
        for (int i = tid; i < 512; i += 256) {
            int r = i >> 3;
            int c = (i & 7) * 4;
            int row = row0 + r;
            float4 v = make_float4(0.f, 0.f, 0.f, 0.f);
            if (row < n)
                v = *(const float4*)&x[(size_t)row * F + kt * 32 + c];
            __half hb[4] = {__float2half_rn(v.x), __float2half_rn(v.y),
                            __float2half_rn(v.z), __float2half_rn(v.w)};
            *(uint2*)&xs[r][c] = *(uint2*)hb;
        }
        // w tile 32x128: 1024 float4, 4 per thread; convert to fp16
        #pragma unroll
        for (int i = tid; i < 1024; i += 256) {
            int r = i >> 5;
            int c = (i & 31) * 4;
            float4 v = *(const float4*)&w[(size_t)(kt * 32 + r) * F + c];
            __half hb[4] = {__float2half_rn(v.x), __float2half_rn(v.y),
                            __float2half_rn(v.z), __float2half_rn(v.w)};
            *(uint2*)&ws[r][c] = *(uint2*)hb;
        }
        __syncthreads();

        #pragma unroll
        for (int ks = 0; ks < 2; ks++) {  // 2 k-steps of 16
            wmma::fragment<wmma::matrix_a, 16, 16, 16, __half,
                           wmma::row_major> a[2];
            #pragma unroll
            for (int i = 0; i < 2; i++)
                wmma::load_matrix_sync(a[i],
                                       &xs[warp_m * 32 + i * 16][ks * 16], 40);
            #pragma unroll
            for (int j = 0; j < 2; j++) {
                wmma::fragment<wmma::matrix_b, 16, 16, 16, __half,
                               wmma::row_major> b;
                wmma::load_matrix_sync(b,
                                       &ws[ks * 16][warp_n * 32 + j * 16], 136);
                #pragma unroll
                for (int i = 0; i < 2; i++)
                    wmma::mma_sync(acc[i][j], a[i], b, acc[i][j]);
            }
        }
        __syncthreads();
    }

    // Epilogue: stage each 16x16 frag (16x20 floats per warp), write fp16
    // support + fp16 bias into g_acc_h (both padded; no row guard needed).
    float* stage = (float*)smem_raw + wid * 320;  // 8*320*4 = 10240 B < 14336
    #pragma unroll
    for (int i = 0; i < 2; i++)
        #pragma unroll
        for (int j = 0; j < 2; j++) {
            wmma::store_matrix_sync(stage, acc[i][j], 20, wmma::mem_row_major);
            __syncwarp();
            int r = lane >> 1;
            int c = (lane & 1) * 8;
            int col0 = warp_n * 32 + j * 16 + c;
            __half hbuf[8];
            #pragma unroll
            for (int q = 0; q < 8; q++)
                hbuf[q] = __float2half_rn(stage[r * 20 + c + q]);
            size_t row = (size_t)row0 + warp_m * 32 + i * 16 + r;
            *(uint4*)&g_support_h[row * F + col0] = *(uint4*)hbuf;
            *(uint4*)&g_acc_h[row * F + col0] = *(uint4*)&bs_h[col0];
            __syncwarp();
        }
}

// ---------------------------------------------------------------------------
// Edge scatter (verbatim R12, the 105.2us pass):
//   g_acc_h[rows[e]] += support_h[cols[e]] * vals[e]  (16B fp16 REDs)
// Warp owns 32 edges, 2 per iteration: lanes 0-15 -> edge 2i, 16-31 -> 2i+1.
// ---------------------------------------------------------------------------
__global__ void __launch_bounds__(256) scatter_kernel(
    const float* __restrict__ vals0, const int* __restrict__ rows0,
    const int* __restrict__ cols0,
    const float* __restrict__ vals1, const int* __restrict__ rows1,
    const int* __restrict__ cols1, int E) {
    int gw = (blockIdx.x * blockDim.x + threadIdx.x) >> 5;
    int lane = threadIdx.x & 31;
    int warps_per_set = (E + 31) >> 5;
    if (gw >= 2 * warps_per_set) return;

    const float* vals;
    const int* rows;
    const int* cols;
    int wset = gw;
    if (gw < warps_per_set) {
        vals = vals0; rows = rows0; cols = cols0;
    } else {
        vals = vals1; rows = rows1; cols = cols1; wset = gw - warps_per_set;
    }
    int base = wset * 32;

    int e = base + lane;
    bool valid = e < E;
    float v = valid ? __ldg(&vals[e]) : 0.f;
    int r = valid ? __ldg(&rows[e]) : 0;
    int c = valid ? __ldg(&cols[e]) : 0;

    int cnt = min(32, E - base);
    int hf = lane >> 4;
    int sub = lane & 15;
    const uint4* sup = (const uint4*)g_support_h;
    int pairs = (cnt + 1) >> 1;

    #pragma unroll 4
    for (int i = 0; i < pairs; i++) {
        int idx = 2 * i + hf;
        int rr = __shfl_sync(0xffffffff, r, idx);
        int cc = __shfl_sync(0xffffffff, c, idx);
        float vv = __shfl_sync(0xffffffff, v, idx);
        if (idx < cnt) {
            uint4 p = __ldg(&sup[(size_t)cc * (F / 8) + sub]);
            u32 pk[4] = {p.x, p.y, p.z, p.w};
            u32 mk[4];
            #pragma unroll
            for (int q = 0; q < 4; q++) {
                float2 f = __half22float2(*(__half2*)&pk[q]);
                __half2 h = __floats2half2_rn(f.x * vv, f.y * vv);
                mk[q] = *(u32*)&h;
            }
            __half* dst = g_acc_h + (size_t)rr * F + sub * 8;
            asm volatile(
                "red.global.add.noftz.v4.f16x2 [%0], {%1,%2,%3,%4};"
                :: "l"(dst), "r"(mk[0]), "r"(mk[1]), "r"(mk[2]), "r"(mk[3])
                : "memory");
        }
    }
}

// ---------------------------------------------------------------------------
// Finalize: out[i] = float(g_acc_h[i])
// ---------------------------------------------------------------------------
__global__ void finalize_kernel(float* __restrict__ out, int n) {
    size_t idx = (size_t)blockIdx.x * blockDim.x + threadIdx.x;
    size_t total = (size_t)n * (F / 4);
    const uint2* acc = (const uint2*)g_acc_h;
    float4* out4 = (float4*)out;
    for (size_t i = idx; i < total; i += (size_t)gridDim.x * blockDim.x) {
        uint2 p = acc[i];
        float2 f01 = __half22float2(*(__half2*)&p.x);
        float2 f23 = __half22float2(*(__half2*)&p.y);
        out4[i] = make_float4(f01.x, f01.y, f23.x, f23.y);
    }
}

// ---------------------------------------------------------------------------
// kernel_launch
// inputs: x, weight, bias, vals0, vals1, rows0, cols0, rows1, cols1
// ---------------------------------------------------------------------------
extern "C" void kernel_launch(void* const* d_in, const int* in_sizes, int n_in,
                              void* d_out, int out_size) {
    const float* x     = (const float*)d_in[0];
    const float* w     = (const float*)d_in[1];
    const float* bias  = (const float*)d_in[2];
    const float* vals0 = (const float*)d_in[3];
    const float* vals1 = (const float*)d_in[4];
    const int* rows0   = (const int*)d_in[5];
    const int* cols0   = (const int*)d_in[6];
    const int* rows1   = (const int*)d_in[7];
    const int* cols1   = (const int*)d_in[8];
    float* out = (float*)d_out;

    int n = in_sizes[0] / F;   // 100000
    int E = in_sizes[3];       // 600000

    // 1) support_h = fp16(x @ W); g_acc_h = half(bias)
    gemm_fp16_kernel<<<(n + 63) / 64, 256>>>(x, w, bias, n);

    // 2) scatter both edge sets (16B packed fp16 REDs)
    long long total_warps = 2LL * ((E + 31) / 32);
    int sblocks = (int)((total_warps * 32 + 255) / 256);
    scatter_kernel<<<sblocks, 256>>>(vals0, rows0, cols0, vals1, rows1, cols1,
                                     E);

    // 3) out = float(g_acc_h)
    finalize_kernel<<<2048, 256>>>(out, n);
}

// round 15
// speedup vs baseline: 1.3365x; 1.0006x over previous
#include <cuda_runtime.h>
#include <cuda_fp16.h>
#include <mma.h>

using namespace nvcuda;

#define F 128
#define N_NODES_MAX 100000
#define N_ROWS_PAD 100096  // 1564 * 64 (GEMM tile M=64)

typedef unsigned int u32;

// fp16 support (only consumer is the scatter)
__device__ __half g_support_h[(size_t)N_ROWS_PAD * F];
// fp16 accumulator: init = half(bias), scatter RED-adds, finalize converts
__device__ __half g_acc_h[(size_t)N_ROWS_PAD * F];
// preconverted fp16 weight
__device__ __half g_wh[F * F];

// ---------------------------------------------------------------------------
// W convert: w -> fp16 (16384 elems)
// ---------------------------------------------------------------------------
__global__ void whalf_kernel(const float* __restrict__ w) {
    int i = blockIdx.x * blockDim.x + threadIdx.x;
    g_wh[i] = __float2half_rn(w[i]);
}

// ---------------------------------------------------------------------------
// GEMM: support_h = fp16(x @ W), FP16 x1, fp32 acc; g_acc_h[row] = half(bias).
// Block 256 thr (8 warps), tile 64(M) x 128(N), warp tile 32x32.
// K tiled 2x64 (only 4 syncthreads/block). W copied preconverted fp16.
// x tile register-prefetched across the 2 K iterations.
// ---------------------------------------------------------------------------
__global__ void __launch_bounds__(256, 2) gemm_fp16_kernel(
    const float* __restrict__ x, const float* __restrict__ bias, int n) {
    __shared__ __align__(16) __half xs[64][72];    // 9.2 KB
    __shared__ __align__(16) __half ws[64][136];   // 17.4 KB
    __shared__ __half bs_h[F];

    const int tid = threadIdx.x;
    const int wid = tid >> 5;
    const int lane = tid & 31;
    const int warp_m = wid & 1;   // 32-row band
    const int warp_n = wid >> 1;  // 32-col band (4 bands)
    const int row0 = blockIdx.x * 64;

    if (tid < F) bs_h[tid] = __float2half_rn(__ldg(&bias[tid]));

    wmma::fragment<wmma::accumulator, 16, 16, 16, float> acc[2][2];
    #pragma unroll
    for (int i = 0; i < 2; i++)
        #pragma unroll
        for (int j = 0; j < 2; j++) wmma::fill_fragment(acc[i][j], 0.0f);

    // prefetch x tile kt=0: 64x64 fp32 = 1024 float4, 4 per thread
    float4 px[4];
    #pragma unroll
    for (int u = 0; u < 4; u++) {
        int i = tid + u * 256;
        int r = i >> 4;           // 16 float4 per row
        int c = (i & 15) * 4;
        int row = row0 + r;
        px[u] = (row < n) ? *(const float4*)&x[(size_t)row * F + c]
                          : make_float4(0.f, 0.f, 0.f, 0.f);
    }

    for (int kt = 0; kt < 2; kt++) {
        // write prefetched x tile to smem as fp16
        #pragma unroll
        for (int u = 0; u < 4; u++) {
            int i = tid + u * 256;
            int r = i >> 4;
            int c = (i & 15) * 4;
            __half hb[4] = {__float2half_rn(px[u].x), __float2half_rn(px[u].y),
                            __float2half_rn(px[u].z), __float2half_rn(px[u].w)};
            *(uint2*)&xs[r][c] = *(uint2*)hb;
        }
        // w tile 64x128 fp16: 1024 uint4, 4 per thread (L2-hot copy)
        #pragma unroll
        for (int u = 0; u < 4; u++) {
            int i = tid + u * 256;
            int r = i >> 4;           // 16 uint4 per row
            int c = (i & 15) * 8;
            *(uint4*)&ws[r][c] =
                *(const uint4*)&g_wh[(size_t)(kt * 64 + r) * F + c];
        }
        __syncthreads();

        // prefetch x tile kt=1 while mma runs on kt=0
        if (kt == 0) {
            #pragma unroll
            for (int u = 0; u < 4; u++) {
                int i = tid + u * 256;
                int r = i >> 4;
                int c = (i & 15) * 4;
                int row = row0 + r;
                px[u] = (row < n)
                            ? *(const float4*)&x[(size_t)row * F + 64 + c]
                            : make_float4(0.f, 0.f, 0.f, 0.f);
            }
        }

        #pragma unroll
        for (int ks = 0; ks < 4; ks++) {  // 4 k-steps of 16
            wmma::fragment<wmma::matrix_a, 16, 16, 16, __half,
                           wmma::row_major> a[2];
            #pragma unroll
            for (int i = 0; i < 2; i++)
                wmma::load_matrix_sync(a[i],
                                       &xs[warp_m * 32 + i * 16][ks * 16], 72);
            #pragma unroll
            for (int j = 0; j < 2; j++) {
                wmma::fragment<wmma::matrix_b, 16, 16, 16, __half,
                               wmma::row_major> b;
                wmma::load_matrix_sync(b,
                                       &ws[ks * 16][warp_n * 32 + j * 16], 136);
                #pragma unroll
                for (int i = 0; i < 2; i++)
                    wmma::mma_sync(acc[i][j], a[i], b, acc[i][j]);
            }
        }
        __syncthreads();
    }

    // Epilogue: stage 16x16 frags via smem (reuse xs), write fp16 support +
    // fp16 bias init of g_acc_h (both buffers row-padded, no guard needed).
    float* stage = (float*)&xs[0][0] + wid * 320;  // 8*320*4 = 10240 B < 9216+...
    #pragma unroll
    for (int i = 0; i < 2; i++)
        #pragma unroll
        for (int j = 0; j < 2; j++) {
            wmma::store_matrix_sync(stage, acc[i][j], 20, wmma::mem_row_major);
            __syncwarp();
            int r = lane >> 1;
            int c = (lane & 1) * 8;
            int col0 = warp_n * 32 + j * 16 + c;
            __half hbuf[8];
            #pragma unroll
            for (int q = 0; q < 8; q++)
                hbuf[q] = __float2half_rn(stage[r * 20 + c + q]);
            size_t row = (size_t)row0 + warp_m * 32 + i * 16 + r;
            *(uint4*)&g_support_h[row * F + col0] = *(uint4*)hbuf;
            *(uint4*)&g_acc_h[row * F + col0] = *(uint4*)&bs_h[col0];
            __syncwarp();
        }
}

// ---------------------------------------------------------------------------
// Edge scatter (verbatim R12/R14):
//   g_acc_h[rows[e]] += support_h[cols[e]] * vals[e]  (16B fp16 REDs)
// ---------------------------------------------------------------------------
__global__ void __launch_bounds__(256) scatter_kernel(
    const float* __restrict__ vals0, const int* __restrict__ rows0,
    const int* __restrict__ cols0,
    const float* __restrict__ vals1, const int* __restrict__ rows1,
    const int* __restrict__ cols1, int E) {
    int gw = (blockIdx.x * blockDim.x + threadIdx.x) >> 5;
    int lane = threadIdx.x & 31;
    int warps_per_set = (E + 31) >> 5;
    if (gw >= 2 * warps_per_set) return;

    const float* vals;
    const int* rows;
    const int* cols;
    int wset = gw;
    if (gw < warps_per_set) {
        vals = vals0; rows = rows0; cols = cols0;
    } else {
        vals = vals1; rows = rows1; cols = cols1; wset = gw - warps_per_set;
    }
    int base = wset * 32;

    int e = base + lane;
    bool valid = e < E;
    float v = valid ? __ldg(&vals[e]) : 0.f;
    int r = valid ? __ldg(&rows[e]) : 0;
    int c = valid ? __ldg(&cols[e]) : 0;

    int cnt = min(32, E - base);
    int hf = lane >> 4;
    int sub = lane & 15;
    const uint4* sup = (const uint4*)g_support_h;
    int pairs = (cnt + 1) >> 1;

    #pragma unroll 4
    for (int i = 0; i < pairs; i++) {
        int idx = 2 * i + hf;
        int rr = __shfl_sync(0xffffffff, r, idx);
        int cc = __shfl_sync(0xffffffff, c, idx);
        float vv = __shfl_sync(0xffffffff, v, idx);
        if (idx < cnt) {
            uint4 p = __ldg(&sup[(size_t)cc * (F / 8) + sub]);
            u32 pk[4] = {p.x, p.y, p.z, p.w};
            u32 mk[4];
            #pragma unroll
            for (int q = 0; q < 4; q++) {
                float2 f = __half22float2(*(__half2*)&pk[q]);
                __half2 h = __floats2half2_rn(f.x * vv, f.y * vv);
                mk[q] = *(u32*)&h;
            }
            __half* dst = g_acc_h + (size_t)rr * F + sub * 8;
            asm volatile(
                "red.global.add.noftz.v4.f16x2 [%0], {%1,%2,%3,%4};"
                :: "l"(dst), "r"(mk[0]), "r"(mk[1]), "r"(mk[2]), "r"(mk[3])
                : "memory");
        }
    }
}

// ---------------------------------------------------------------------------
// Finalize: out[i] = float(g_acc_h[i])   (verbatim)
// ---------------------------------------------------------------------------
__global__ void finalize_kernel(float* __restrict__ out, int n) {
    size_t idx = (size_t)blockIdx.x * blockDim.x + threadIdx.x;
    size_t total = (size_t)n * (F / 4);
    const uint2* acc = (const uint2*)g_acc_h;
    float4* out4 = (float4*)out;
    for (size_t i = idx; i < total; i += (size_t)gridDim.x * blockDim.x) {
        uint2 p = acc[i];
        float2 f01 = __half22float2(*(__half2*)&p.x);
        float2 f23 = __half22float2(*(__half2*)&p.y);
        out4[i] = make_float4(f01.x, f01.y, f23.x, f23.y);
    }
}

// ---------------------------------------------------------------------------
// kernel_launch
// inputs: x, weight, bias, vals0, vals1, rows0, cols0, rows1, cols1
// ---------------------------------------------------------------------------
extern "C" void kernel_launch(void* const* d_in, const int* in_sizes, int n_in,
                              void* d_out, int out_size) {
    const float* x     = (const float*)d_in[0];
    const float* w     = (const float*)d_in[1];
    const float* bias  = (const float*)d_in[2];
    const float* vals0 = (const float*)d_in[3];
    const float* vals1 = (const float*)d_in[4];
    const int* rows0   = (const int*)d_in[5];
    const int* cols0   = (const int*)d_in[6];
    const int* rows1   = (const int*)d_in[7];
    const int* cols1   = (const int*)d_in[8];
    float* out = (float*)d_out;

    int n = in_sizes[0] / F;   // 100000
    int E = in_sizes[3];       // 600000

    // 1) W -> fp16; support_h = fp16(x @ W); g_acc_h = half(bias)
    whalf_kernel<<<(F * F) / 256, 256>>>(w);
    gemm_fp16_kernel<<<(n + 63) / 64, 256>>>(x, bias, n);

    // 2) scatter both edge sets (16B packed fp16 REDs)
    long long total_warps = 2LL * ((E + 31) / 32);
    int sblocks = (int)((total_warps * 32 + 255) / 256);
    scatter_kernel<<<sblocks, 256>>>(vals0, rows0, cols0, vals1, rows1, cols1,
                                     E);

    // 3) out = float(g_acc_h)
    finalize_kernel<<<2048, 256>>>(out, n);
}

// round 16
// speedup vs baseline: 1.3527x; 1.0121x over previous
#include <cuda_runtime.h>
#include <cuda_fp16.h>
#include <mma.h>

using namespace nvcuda;

#define F 128
#define N_NODES_MAX 100000
#define N_ROWS_PAD 100096  // 1564 * 64 (GEMM tile M=64)

typedef unsigned int u32;

// fp16 support (only consumer is the scatter)
__device__ __half g_support_h[(size_t)N_ROWS_PAD * F];
// fp16 accumulator: init = half(bias), scatter RED-adds, finalize converts
__device__ __half g_acc_h[(size_t)N_ROWS_PAD * F];

// ---------------------------------------------------------------------------
// GEMM: support_h = fp16(x @ W), FP16 x1, fp32 acc; g_acc_h[row] = half(bias).
// Block 256 thr (8 warps), tile 64(M) x 128(N), warp tile 32x32.
// K tiled 2x64 (4 syncthreads/block). x register-prefetched; W converted
// fp32->fp16 inline in the kt loop (L2-hot, no separate kernel).
// ---------------------------------------------------------------------------
__global__ void __launch_bounds__(256, 2) gemm_fp16_kernel(
    const float* __restrict__ x, const float* __restrict__ w,
    const float* __restrict__ bias, int n) {
    __shared__ __align__(16) __half xs[64][72];    // 9.2 KB
    __shared__ __align__(16) __half ws[64][136];   // 17.4 KB
    __shared__ __half bs_h[F];

    const int tid = threadIdx.x;
    const int wid = tid >> 5;
    const int lane = tid & 31;
    const int warp_m = wid & 1;   // 32-row band
    const int warp_n = wid >> 1;  // 32-col band (4 bands)
    const int row0 = blockIdx.x * 64;

    if (tid < F) bs_h[tid] = __float2half_rn(__ldg(&bias[tid]));

    wmma::fragment<wmma::accumulator, 16, 16, 16, float> acc[2][2];
    #pragma unroll
    for (int i = 0; i < 2; i++)
        #pragma unroll
        for (int j = 0; j < 2; j++) wmma::fill_fragment(acc[i][j], 0.0f);

    // prefetch x tile kt=0: 64x64 fp32 = 1024 float4, 4 per thread
    float4 px[4];
    #pragma unroll
    for (int u = 0; u < 4; u++) {
        int i = tid + u * 256;
        int r = i >> 4;           // 16 float4 per row
        int c = (i & 15) * 4;
        int row = row0 + r;
        px[u] = (row < n) ? *(const float4*)&x[(size_t)row * F + c]
                          : make_float4(0.f, 0.f, 0.f, 0.f);
    }

    for (int kt = 0; kt < 2; kt++) {
        // write prefetched x tile to smem as fp16
        #pragma unroll
        for (int u = 0; u < 4; u++) {
            int i = tid + u * 256;
            int r = i >> 4;
            int c = (i & 15) * 4;
            __half hb[4] = {__float2half_rn(px[u].x), __float2half_rn(px[u].y),
                            __float2half_rn(px[u].z), __float2half_rn(px[u].w)};
            *(uint2*)&xs[r][c] = *(uint2*)hb;
        }
        // w tile 64x128 fp32 -> fp16 inline: 2048 float4, 8 per thread
        #pragma unroll
        for (int u = 0; u < 8; u++) {
            int i = tid + u * 256;
            int r = i >> 5;           // 32 float4 per row
            int c = (i & 31) * 4;
            float4 v = *(const float4*)&w[(size_t)(kt * 64 + r) * F + c];
            __half hb[4] = {__float2half_rn(v.x), __float2half_rn(v.y),
                            __float2half_rn(v.z), __float2half_rn(v.w)};
            *(uint2*)&ws[r][c] = *(uint2*)hb;
        }
        __syncthreads();

        // prefetch x tile kt=1 while mma runs on kt=0
        if (kt == 0) {
            #pragma unroll
            for (int u = 0; u < 4; u++) {
                int i = tid + u * 256;
                int r = i >> 4;
                int c = (i & 15) * 4;
                int row = row0 + r;
                px[u] = (row < n)
                            ? *(const float4*)&x[(size_t)row * F + 64 + c]
                            : make_float4(0.f, 0.f, 0.f, 0.f);
            }
        }

        #pragma unroll
        for (int ks = 0; ks < 4; ks++) {  // 4 k-steps of 16
            wmma::fragment<wmma::matrix_a, 16, 16, 16, __half,
                           wmma::row_major> a[2];
            #pragma unroll
            for (int i = 0; i < 2; i++)
                wmma::load_matrix_sync(a[i],
                                       &xs[warp_m * 32 + i * 16][ks * 16], 72);
            #pragma unroll
            for (int j = 0; j < 2; j++) {
                wmma::fragment<wmma::matrix_b, 16, 16, 16, __half,
                               wmma::row_major> b;
                wmma::load_matrix_sync(b,
                                       &ws[ks * 16][warp_n * 32 + j * 16], 136);
                #pragma unroll
                for (int i = 0; i < 2; i++)
                    wmma::mma_sync(acc[i][j], a[i], b, acc[i][j]);
            }
        }
        __syncthreads();
    }

    // Epilogue: stage 16x16 frags via smem (reuse xs), write fp16 support +
    // fp16 bias init of g_acc_h (both buffers row-padded, no guard needed).
    float* stage = (float*)&xs[0][0] + wid * 320;
    #pragma unroll
    for (int i = 0; i < 2; i++)
        #pragma unroll
        for (int j = 0; j < 2; j++) {
            wmma::store_matrix_sync(stage, acc[i][j], 20, wmma::mem_row_major);
            __syncwarp();
            int r = lane >> 1;
            int c = (lane & 1) * 8;
            int col0 = warp_n * 32 + j * 16 + c;
            __half hbuf[8];
            #pragma unroll
            for (int q = 0; q < 8; q++)
                hbuf[q] = __float2half_rn(stage[r * 20 + c + q]);
            size_t row = (size_t)row0 + warp_m * 32 + i * 16 + r;
            *(uint4*)&g_support_h[row * F + col0] = *(uint4*)hbuf;
            *(uint4*)&g_acc_h[row * F + col0] = *(uint4*)&bs_h[col0];
            __syncwarp();
        }
}

// ---------------------------------------------------------------------------
// Edge scatter (verbatim R12/R14/R15):
//   g_acc_h[rows[e]] += support_h[cols[e]] * vals[e]  (16B fp16 REDs)
// ---------------------------------------------------------------------------
__global__ void __launch_bounds__(256) scatter_kernel(
    const float* __restrict__ vals0, const int* __restrict__ rows0,
    const int* __restrict__ cols0,
    const float* __restrict__ vals1, const int* __restrict__ rows1,
    const int* __restrict__ cols1, int E) {
    int gw = (blockIdx.x * blockDim.x + threadIdx.x) >> 5;
    int lane = threadIdx.x & 31;
    int warps_per_set = (E + 31) >> 5;
    if (gw >= 2 * warps_per_set) return;

    const float* vals;
    const int* rows;
    const int* cols;
    int wset = gw;
    if (gw < warps_per_set) {
        vals = vals0; rows = rows0; cols = cols0;
    } else {
        vals = vals1; rows = rows1; cols = cols1; wset = gw - warps_per_set;
    }
    int base = wset * 32;

    int e = base + lane;
    bool valid = e < E;
    float v = valid ? __ldg(&vals[e]) : 0.f;
    int r = valid ? __ldg(&rows[e]) : 0;
    int c = valid ? __ldg(&cols[e]) : 0;

    int cnt = min(32, E - base);
    int hf = lane >> 4;
    int sub = lane & 15;
    const uint4* sup = (const uint4*)g_support_h;
    int pairs = (cnt + 1) >> 1;

    #pragma unroll 4
    for (int i = 0; i < pairs; i++) {
        int idx = 2 * i + hf;
        int rr = __shfl_sync(0xffffffff, r, idx);
        int cc = __shfl_sync(0xffffffff, c, idx);
        float vv = __shfl_sync(0xffffffff, v, idx);
        if (idx < cnt) {
            uint4 p = __ldg(&sup[(size_t)cc * (F / 8) + sub]);
            u32 pk[4] = {p.x, p.y, p.z, p.w};
            u32 mk[4];
            #pragma unroll
            for (int q = 0; q < 4; q++) {
                float2 f = __half22float2(*(__half2*)&pk[q]);
                __half2 h = __floats2half2_rn(f.x * vv, f.y * vv);
                mk[q] = *(u32*)&h;
            }
            __half* dst = g_acc_h + (size_t)rr * F + sub * 8;
            asm volatile(
                "red.global.add.noftz.v4.f16x2 [%0], {%1,%2,%3,%4};"
                :: "l"(dst), "r"(mk[0]), "r"(mk[1]), "r"(mk[2]), "r"(mk[3])
                : "memory");
        }
    }
}

// ---------------------------------------------------------------------------
// Finalize: out[i] = float(g_acc_h[i]) — one uint2 (4 halves) per thread,
// no grid-stride loop.
// ---------------------------------------------------------------------------
__global__ void __launch_bounds__(256) finalize_kernel(float* __restrict__ out,
                                                       int n) {
    size_t i = (size_t)blockIdx.x * blockDim.x + threadIdx.x;
    size_t total = (size_t)n * (F / 4);
    if (i >= total) return;
    uint2 p = ((const uint2*)g_acc_h)[i];
    float2 f01 = __half22float2(*(__half2*)&p.x);
    float2 f23 = __half22float2(*(__half2*)&p.y);
    ((float4*)out)[i] = make_float4(f01.x, f01.y, f23.x, f23.y);
}

// ---------------------------------------------------------------------------
// kernel_launch
// inputs: x, weight, bias, vals0, vals1, rows0, cols0, rows1, cols1
// ---------------------------------------------------------------------------
extern "C" void kernel_launch(void* const* d_in, const int* in_sizes, int n_in,
                              void* d_out, int out_size) {
    const float* x     = (const float*)d_in[0];
    const float* w     = (const float*)d_in[1];
    const float* bias  = (const float*)d_in[2];
    const float* vals0 = (const float*)d_in[3];
    const float* vals1 = (const float*)d_in[4];
    const int* rows0   = (const int*)d_in[5];
    const int* cols0   = (const int*)d_in[6];
    const int* rows1   = (const int*)d_in[7];
    const int* cols1   = (const int*)d_in[8];
    float* out = (float*)d_out;

    int n = in_sizes[0] / F;   // 100000
    int E = in_sizes[3];       // 600000

    // 1) support_h = fp16(x @ W); g_acc_h = half(bias); W converted inline
    gemm_fp16_kernel<<<(n + 63) / 64, 256>>>(x, w, bias, n);

    // 2) scatter both edge sets (16B packed fp16 REDs)
    long long total_warps = 2LL * ((E + 31) / 32);
    int sblocks = (int)((total_warps * 32 + 255) / 256);
    scatter_kernel<<<sblocks, 256>>>(vals0, rows0, cols0, vals1, rows1, cols1,
                                     E);

    // 3) out = float(g_acc_h), one vec4 per thread
    int fthreads = n * (F / 4);
    finalize_kernel<<<(fthreads + 255) / 256, 256>>>(out, n);
}

// round 17
// speedup vs baseline: 1.3902x; 1.0277x over previous
#include <cuda_runtime.h>
#include <cuda_fp16.h>
#include <mma.h>

using namespace nvcuda;

#define F 128
#define N_NODES_MAX 100000
#define N_ROWS_PAD 100096  // 1564 * 64 (GEMM tile M=64)

typedef unsigned int u32;

// fp16 support (only consumer is the scatter)
__device__ __half g_support_h[(size_t)N_ROWS_PAD * F];
// fp16 accumulator: init = half(bias), scatter RED-adds, finalize converts
__device__ __half g_acc_h[(size_t)N_ROWS_PAD * F];
// preconverted fp16 weight (cp.async source)
__device__ __half g_wh[F * F];

// ---------------------------------------------------------------------------
// W convert: w -> fp16 (16384 elems)
// ---------------------------------------------------------------------------
__global__ void whalf_kernel(const float* __restrict__ w) {
    int i = blockIdx.x * blockDim.x + threadIdx.x;
    g_wh[i] = __float2half_rn(w[i]);
}

// ---------------------------------------------------------------------------
// GEMM: support_h = fp16(x @ W), FP16 x1, fp32 acc; g_acc_h[row] = half(bias).
// Block 256 thr (8 warps), tile 64(M) x 128(N), warp tile 32x32, 2 CTAs/SM.
// K split in 2 tiles of 64. BOTH ws tiles fetched via cp.async (double
// buffered, issued at kernel start -> W latency fully off the critical path).
// x register-prefetched + converted to fp16 in the fill.
// ---------------------------------------------------------------------------
__global__ void __launch_bounds__(256, 2) gemm_fp16_kernel(
    const float* __restrict__ x, const float* __restrict__ bias, int n) {
    // layout: xs[64][72] | ws0[64][136] | ws1[64][136] | bs_h[128]
    __shared__ __align__(16) char smem_raw[9216 + 17408 + 17408 + 256];

    __half (*xs)[72] = (__half(*)[72])smem_raw;
    char* ws0_raw = smem_raw + 9216;
    char* ws1_raw = smem_raw + 9216 + 17408;
    __half (*ws0)[136] = (__half(*)[136])ws0_raw;
    __half (*ws1)[136] = (__half(*)[136])ws1_raw;
    __half* bs_h = (__half*)(smem_raw + 9216 + 17408 + 17408);

    const int tid = threadIdx.x;
    const int wid = tid >> 5;
    const int lane = tid & 31;
    const int warp_m = wid & 1;   // 32-row band
    const int warp_n = wid >> 1;  // 32-col band (4 bands)
    const int row0 = blockIdx.x * 64;

    // Issue cp.async for BOTH W tiles immediately (fp16 raw bytes, 16B chunks)
    // tile = 64 rows x 256B; smem row stride 272B. 1024 chunks, 4 per thread.
    const char* wsrc = (const char*)g_wh;
    #pragma unroll
    for (int u = 0; u < 4; u++) {
        int i = tid + u * 256;
        int r = i >> 4;
        int cb = (i & 15) * 16;
        u32 dst = (u32)__cvta_generic_to_shared(ws0_raw + r * 272 + cb);
        asm volatile("cp.async.cg.shared.global [%0], [%1], 16;"
                     :: "r"(dst), "l"(wsrc + r * 256 + cb));
    }
    asm volatile("cp.async.commit_group;");
    #pragma unroll
    for (int u = 0; u < 4; u++) {
        int i = tid + u * 256;
        int r = i >> 4;
        int cb = (i & 15) * 16;
        u32 dst = (u32)__cvta_generic_to_shared(ws1_raw + r * 272 + cb);
        asm volatile("cp.async.cg.shared.global [%0], [%1], 16;"
                     :: "r"(dst), "l"(wsrc + (64 + r) * 256 + cb));
    }
    asm volatile("cp.async.commit_group;");

    if (tid < F) bs_h[tid] = __float2half_rn(__ldg(&bias[tid]));

    wmma::fragment<wmma::accumulator, 16, 16, 16, float> acc[2][2];
    #pragma unroll
    for (int i = 0; i < 2; i++)
        #pragma unroll
        for (int j = 0; j < 2; j++) wmma::fill_fragment(acc[i][j], 0.0f);

    // prefetch x tile 0: 64x64 fp32 = 1024 float4, 4 per thread
    float4 px[4];
    #pragma unroll
    for (int u = 0; u < 4; u++) {
        int i = tid + u * 256;
        int r = i >> 4;
        int c = (i & 15) * 4;
        int row = row0 + r;
        px[u] = (row < n) ? *(const float4*)&x[(size_t)row * F + c]
                          : make_float4(0.f, 0.f, 0.f, 0.f);
    }
    // fill xs with tile 0 (fp16)
    #pragma unroll
    for (int u = 0; u < 4; u++) {
        int i = tid + u * 256;
        int r = i >> 4;
        int c = (i & 15) * 4;
        __half hb[4] = {__float2half_rn(px[u].x), __float2half_rn(px[u].y),
                        __float2half_rn(px[u].z), __float2half_rn(px[u].w)};
        *(uint2*)&xs[r][c] = *(uint2*)hb;
    }
    asm volatile("cp.async.wait_group 1;");  // ws0 resident
    __syncthreads();

    // prefetch x tile 1 while mma on tile 0
    #pragma unroll
    for (int u = 0; u < 4; u++) {
        int i = tid + u * 256;
        int r = i >> 4;
        int c = (i & 15) * 4;
        int row = row0 + r;
        px[u] = (row < n) ? *(const float4*)&x[(size_t)row * F + 64 + c]
                          : make_float4(0.f, 0.f, 0.f, 0.f);
    }

    #pragma unroll
    for (int ks = 0; ks < 4; ks++) {  // K tile 0: 4 k-steps of 16
        wmma::fragment<wmma::matrix_a, 16, 16, 16, __half,
                       wmma::row_major> a[2];
        #pragma unroll
        for (int i = 0; i < 2; i++)
            wmma::load_matrix_sync(a[i],
                                   &xs[warp_m * 32 + i * 16][ks * 16], 72);
        #pragma unroll
        for (int j = 0; j < 2; j++) {
            wmma::fragment<wmma::matrix_b, 16, 16, 16, __half,
                           wmma::row_major> b;
            wmma::load_matrix_sync(b, &ws0[ks * 16][warp_n * 32 + j * 16], 136);
            #pragma unroll
            for (int i = 0; i < 2; i++)
                wmma::mma_sync(acc[i][j], a[i], b, acc[i][j]);
        }
    }
    __syncthreads();

    // fill xs with tile 1
    #pragma unroll
    for (int u = 0; u < 4; u++) {
        int i = tid + u * 256;
        int r = i >> 4;
        int c = (i & 15) * 4;
        __half hb[4] = {__float2half_rn(px[u].x), __float2half_rn(px[u].y),
                        __float2half_rn(px[u].z), __float2half_rn(px[u].w)};
        *(uint2*)&xs[r][c] = *(uint2*)hb;
    }
    asm volatile("cp.async.wait_group 0;");  // ws1 resident
    __syncthreads();

    #pragma unroll
    for (int ks = 0; ks < 4; ks++) {  // K tile 1
        wmma::fragment<wmma::matrix_a, 16, 16, 16, __half,
                       wmma::row_major> a[2];
        #pragma unroll
        for (int i = 0; i < 2; i++)
            wmma::load_matrix_sync(a[i],
                                   &xs[warp_m * 32 + i * 16][ks * 16], 72);
        #pragma unroll
        for (int j = 0; j < 2; j++) {
            wmma::fragment<wmma::matrix_b, 16, 16, 16, __half,
                           wmma::row_major> b;
            wmma::load_matrix_sync(b, &ws1[ks * 16][warp_n * 32 + j * 16], 136);
            #pragma unroll
            for (int i = 0; i < 2; i++)
                wmma::mma_sync(acc[i][j], a[i], b, acc[i][j]);
        }
    }
    __syncthreads();

    // Epilogue: stage 16x16 frags via smem, write fp16 support + bias init.
    float* stage = (float*)smem_raw + wid * 320;  // 10240 B, xs/ws0 region
    #pragma unroll
    for (int i = 0; i < 2; i++)
        #pragma unroll
        for (int j = 0; j < 2; j++) {
            wmma::store_matrix_sync(stage, acc[i][j], 20, wmma::mem_row_major);
            __syncwarp();
            int r = lane >> 1;
            int c = (lane & 1) * 8;
            int col0 = warp_n * 32 + j * 16 + c;
            __half hbuf[8];
            #pragma unroll
            for (int q = 0; q < 8; q++)
                hbuf[q] = __float2half_rn(stage[r * 20 + c + q]);
            size_t row = (size_t)row0 + warp_m * 32 + i * 16 + r;
            *(uint4*)&g_support_h[row * F + col0] = *(uint4*)hbuf;
            *(uint4*)&g_acc_h[row * F + col0] = *(uint4*)&bs_h[col0];
            __syncwarp();
        }
}

// ---------------------------------------------------------------------------
// Edge scatter (verbatim R12..R16):
//   g_acc_h[rows[e]] += support_h[cols[e]] * vals[e]  (16B fp16 REDs)
// ---------------------------------------------------------------------------
__global__ void __launch_bounds__(256) scatter_kernel(
    const float* __restrict__ vals0, const int* __restrict__ rows0,
    const int* __restrict__ cols0,
    const float* __restrict__ vals1, const int* __restrict__ rows1,
    const int* __restrict__ cols1, int E) {
    int gw = (blockIdx.x * blockDim.x + threadIdx.x) >> 5;
    int lane = threadIdx.x & 31;
    int warps_per_set = (E + 31) >> 5;
    if (gw >= 2 * warps_per_set) return;

    const float* vals;
    const int* rows;
    const int* cols;
    int wset = gw;
    if (gw < warps_per_set) {
        vals = vals0; rows = rows0; cols = cols0;
    } else {
        vals = vals1; rows = rows1; cols = cols1; wset = gw - warps_per_set;
    }
    int base = wset * 32;

    int e = base + lane;
    bool valid = e < E;
    float v = valid ? __ldg(&vals[e]) : 0.f;
    int r = valid ? __ldg(&rows[e]) : 0;
    int c = valid ? __ldg(&cols[e]) : 0;

    int cnt = min(32, E - base);
    int hf = lane >> 4;
    int sub = lane & 15;
    const uint4* sup = (const uint4*)g_support_h;
    int pairs = (cnt + 1) >> 1;

    #pragma unroll 4
    for (int i = 0; i < pairs; i++) {
        int idx = 2 * i + hf;
        int rr = __shfl_sync(0xffffffff, r, idx);
        int cc = __shfl_sync(0xffffffff, c, idx);
        float vv = __shfl_sync(0xffffffff, v, idx);
        if (idx < cnt) {
            uint4 p = __ldg(&sup[(size_t)cc * (F / 8) + sub]);
            u32 pk[4] = {p.x, p.y, p.z, p.w};
            u32 mk[4];
            #pragma unroll
            for (int q = 0; q < 4; q++) {
                float2 f = __half22float2(*(__half2*)&pk[q]);
                __half2 h = __floats2half2_rn(f.x * vv, f.y * vv);
                mk[q] = *(u32*)&h;
            }
            __half* dst = g_acc_h + (size_t)rr * F + sub * 8;
            asm volatile(
                "red.global.add.noftz.v4.f16x2 [%0], {%1,%2,%3,%4};"
                :: "l"(dst), "r"(mk[0]), "r"(mk[1]), "r"(mk[2]), "r"(mk[3])
                : "memory");
        }
    }
}

// ---------------------------------------------------------------------------
// Finalize (verbatim R16): out[i] = float(g_acc_h[i]), one vec4 per thread.
// ---------------------------------------------------------------------------
__global__ void __launch_bounds__(256) finalize_kernel(float* __restrict__ out,
                                                       int n) {
    size_t i = (size_t)blockIdx.x * blockDim.x + threadIdx.x;
    size_t total = (size_t)n * (F / 4);
    if (i >= total) return;
    uint2 p = ((const uint2*)g_acc_h)[i];
    float2 f01 = __half22float2(*(__half2*)&p.x);
    float2 f23 = __half22float2(*(__half2*)&p.y);
    ((float4*)out)[i] = make_float4(f01.x, f01.y, f23.x, f23.y);
}

// ---------------------------------------------------------------------------
// kernel_launch
// inputs: x, weight, bias, vals0, vals1, rows0, cols0, rows1, cols1
// ---------------------------------------------------------------------------
extern "C" void kernel_launch(void* const* d_in, const int* in_sizes, int n_in,
                              void* d_out, int out_size) {
    const float* x     = (const float*)d_in[0];
    const float* w     = (const float*)d_in[1];
    const float* bias  = (const float*)d_in[2];
    const float* vals0 = (const float*)d_in[3];
    const float* vals1 = (const float*)d_in[4];
    const int* rows0   = (const int*)d_in[5];
    const int* cols0   = (const int*)d_in[6];
    const int* rows1   = (const int*)d_in[7];
    const int* cols1   = (const int*)d_in[8];
    float* out = (float*)d_out;

    int n = in_sizes[0] / F;   // 100000
    int E = in_sizes[3];       // 600000

    // 1) W -> fp16; support_h = fp16(x @ W); g_acc_h = half(bias)
    whalf_kernel<<<(F * F) / 256, 256>>>(w);
    gemm_fp16_kernel<<<(n + 63) / 64, 256>>>(x, bias, n);

    // 2) scatter both edge sets (16B packed fp16 REDs)
    long long total_warps = 2LL * ((E + 31) / 32);
    int sblocks = (int)((total_warps * 32 + 255) / 256);
    scatter_kernel<<<sblocks, 256>>>(vals0, rows0, cols0, vals1, rows1, cols1,
                                     E);

    // 3) out = float(g_acc_h), one vec4 per thread
    int fthreads = n * (F / 4);
    finalize_kernel<<<(fthreads + 255) / 256, 256>>>(out, n);
}